// round 17
// baseline (speedup 1.0000x reference)
#include <cuda_runtime.h>

// LieTransport bilinear backward warp — binned 16x16 tiles + SMEM halos, v3.
// Flat-kernel floor is LTS bytes (1.32GB @ ~12.4TB/s ≈ 106us); only cross-
// pixel tap dedup can beat it. v3 fixes v2's staging:work ratio (16px tiles:
// halo/tile = 1.13 vs 2.3), uses 2-channel groups (37.8KB smem, 6 blocks/SM)
// and 4-records-per-warp iterations with conflict-free LDS.

#define Hd 128
#define Wd 128
#define Cd 64
#define HWd (Hd * Wd)
#define NPIX (4 * HWd)
#define NTILE 256                  // 4 batches x 8x8 tiles of 16x16 px
#define CAP 4096
#define CHUNK 256
#define NCHUNK (CAP / CHUNK)       // 16

#define ROW_F4 69                  // 17 px * 4 quarters + 1 pad
#define CH_F4  1180                // >= 17*69, ≡ 4 (mod 8) -> conflict-free
#define SM_F4  (2 * CH_F4)         // 2360 float4 = 37,760 B

__device__ unsigned g_cnt[NTILE];
__device__ unsigned g_ovfn;
__device__ uint4    g_rec[NTILE * CAP];   // 16 MB
__device__ uint4    g_ovf[NPIX];

// ---- K0: zero counters ----
__global__ void k_zero()
{
    g_cnt[threadIdx.x] = 0u;
    if (threadIdx.x == 0) g_ovfn = 0u;
}

// ---- K1: bin pixels by 16x16 tap tile ----
__global__ __launch_bounds__(256) void k_bin(
    const float* __restrict__ flow, const float* __restrict__ dt)
{
    const int pid = blockIdx.x * 256 + threadIdx.x;
    const int b = pid >> 14;
    const int y = (pid >> 7) & (Hd - 1);
    const int x = pid & (Wd - 1);

    const float d   = dt[b];
    const float d64 = d * 64.0f;
    const int   fb  = ((b * 2) * Hd + y) * Wd + x;
    const float fx  = flow[fb];
    const float fy  = flow[fb + HWd];

    const float ix = fminf(fmaxf(
        fmaf((float)x, 128.0f / 127.0f, fmaf(-fx, d64, -0.5f)), 0.0f), 127.0f);
    const float iy = fminf(fmaxf(
        fmaf((float)y, 128.0f / 127.0f, fmaf(-fy, d64, -0.5f)), 0.0f), 127.0f);

    const float x0f = floorf(ix);
    const float y0f = floorf(iy);
    const int x0 = (int)x0f;
    const int y0 = (int)y0f;
    const int tile = b * 64 + (y0 >> 4) * 8 + (x0 >> 4);

    uint4 rec;
    rec.x = (unsigned)x | ((unsigned)y << 7) | ((unsigned)x0 << 14) | ((unsigned)y0 << 21);
    rec.y = (unsigned)b;
    rec.z = __float_as_uint(ix - x0f);
    rec.w = __float_as_uint(iy - y0f);

    const unsigned rank = atomicAdd(&g_cnt[tile], 1u);
    if (rank < CAP) {
        g_rec[tile * CAP + rank] = rec;
    } else {
        const unsigned o = atomicAdd(&g_ovfn, 1u);
        g_ovf[o] = rec;
    }
}

// ---- K2: staged gather. Block = (tile, 2-channel group, record chunk) ----
__global__ __launch_bounds__(256) void k_gather(
    const float4* __restrict__ h4, float4* __restrict__ out4)
{
    __shared__ float4 s[SM_F4];

    const int tile = blockIdx.x;            // 0..255
    const int cg   = blockIdx.y;            // 0..31 -> channels cg*2, cg*2+1
    const int ck   = blockIdx.z;            // record chunk

    const unsigned n  = min(g_cnt[tile], (unsigned)CAP);
    const unsigned c0 = (unsigned)(ck * CHUNK);
    if (c0 >= n) return;                    // dead chunk: cheap exit
    const unsigned c1 = min(c0 + (unsigned)CHUNK, n);

    const int b   = tile >> 6;
    const int ty  = ((tile >> 3) & 7) * 16;
    const int tx  = (tile & 7) * 16;
    const int tid = threadIdx.x;
    const int ch0 = cg * 2;

    // ---- stage halo: 2 ch x 17 rows x 17 px x 4 q = 2312 float4 ----
    for (int idx = tid; idx < 2 * 17 * 68; idx += 256) {
        const int u   = idx / 1156;          // channel sub 0..1
        const int rem = idx - u * 1156;
        const int row = rem / 68;            // halo row 0..16
        const int i   = rem - row * 68;      // px*4 + q
        const int gy  = min(ty + row, 127);
        const int gx  = min(tx + (i >> 2), 127);
        const int plane = (b * Cd + ch0 + u) * HWd;
        s[u * CH_F4 + row * ROW_F4 + i] =
            __ldg(h4 + (plane + gy * Wd + gx) * 4 + (i & 3));
    }
    __syncthreads();

    // ---- sample: warp iteration = 4 records x 2 ch x 4 quarters ----
    const int w    = tid >> 5;
    const int lane = tid & 31;
    const int r    = lane >> 3;              // record sub 0..3
    const int u    = (lane >> 2) & 1;        // channel sub 0..1
    const int q    = lane & 3;               // float4 quarter
    const int plane = (b * Cd + ch0 + u) * HWd;
    const int sbase = u * CH_F4;
    const unsigned rbase = (unsigned)tile * CAP;

    for (unsigned i = c0 + (unsigned)(w * 4); i < c1; i += 32) {
        const unsigned ri = i + (unsigned)r;
        const bool active = ri < c1;
        const uint4 rec = g_rec[rbase + (active ? ri : (c1 - 1))];

        const int x  = rec.x & 127;
        const int y  = (rec.x >> 7) & 127;
        const int x0 = (rec.x >> 14) & 127;
        const int y0 = (rec.x >> 21) & 127;
        const float wx = __uint_as_float(rec.z);
        const float wy = __uint_as_float(rec.w);

        const int px0 = x0 - tx;
        const int py0 = y0 - ty;
        const int px1 = min(x0 + 1, 127) - tx;
        const int py1 = min(y0 + 1, 127) - ty;

        const float4 v00 = s[sbase + py0 * ROW_F4 + px0 * 4 + q];
        const float4 v01 = s[sbase + py0 * ROW_F4 + px1 * 4 + q];
        const float4 v10 = s[sbase + py1 * ROW_F4 + px0 * 4 + q];
        const float4 v11 = s[sbase + py1 * ROW_F4 + px1 * 4 + q];

        float4 top, bot, res;
        top.x = fmaf(wx, v01.x - v00.x, v00.x);
        top.y = fmaf(wx, v01.y - v00.y, v00.y);
        top.z = fmaf(wx, v01.z - v00.z, v00.z);
        top.w = fmaf(wx, v01.w - v00.w, v00.w);
        bot.x = fmaf(wx, v11.x - v10.x, v10.x);
        bot.y = fmaf(wx, v11.y - v10.y, v10.y);
        bot.z = fmaf(wx, v11.z - v10.z, v10.z);
        bot.w = fmaf(wx, v11.w - v10.w, v10.w);
        res.x = fmaf(wy, bot.x - top.x, top.x);
        res.y = fmaf(wy, bot.y - top.y, top.y);
        res.z = fmaf(wy, bot.z - top.z, top.z);
        res.w = fmaf(wy, bot.w - top.w, top.w);

        if (active)
            __stcs(out4 + (plane + y * Wd + x) * 4 + q, res);
    }
}

// ---- K3: overflow backstop, thread per (record, channel, quarter) ----
__global__ __launch_bounds__(256) void k_overflow(
    const float4* __restrict__ h4, float4* __restrict__ out4)
{
    const unsigned n = g_ovfn;
    if (n == 0) return;
    const unsigned total  = n * Cd * 4;
    const unsigned stride = gridDim.x * 256;
    for (unsigned idx = blockIdx.x * 256 + threadIdx.x; idx < total; idx += stride) {
        const uint4 rec = g_ovf[idx / (Cd * 4)];
        const int rem = idx & (Cd * 4 - 1);
        const int ch  = rem >> 2;
        const int q   = rem & 3;

        const int b  = (int)rec.y;
        const int x  = rec.x & 127;
        const int y  = (rec.x >> 7) & 127;
        const int x0 = (rec.x >> 14) & 127;
        const int y0 = (rec.x >> 21) & 127;
        const float wx = __uint_as_float(rec.z);
        const float wy = __uint_as_float(rec.w);
        const int x1 = min(x0 + 1, 127);
        const int y1 = min(y0 + 1, 127);

        const int plane = (b * Cd + ch) * HWd;
        const float4 v00 = __ldg(h4 + (plane + y0 * Wd + x0) * 4 + q);
        const float4 v01 = __ldg(h4 + (plane + y0 * Wd + x1) * 4 + q);
        const float4 v10 = __ldg(h4 + (plane + y1 * Wd + x0) * 4 + q);
        const float4 v11 = __ldg(h4 + (plane + y1 * Wd + x1) * 4 + q);

        float4 top, bot, res;
        top.x = fmaf(wx, v01.x - v00.x, v00.x);
        top.y = fmaf(wx, v01.y - v00.y, v00.y);
        top.z = fmaf(wx, v01.z - v00.z, v00.z);
        top.w = fmaf(wx, v01.w - v00.w, v00.w);
        bot.x = fmaf(wx, v11.x - v10.x, v10.x);
        bot.y = fmaf(wx, v11.y - v10.y, v10.y);
        bot.z = fmaf(wx, v11.z - v10.z, v10.z);
        bot.w = fmaf(wx, v11.w - v10.w, v10.w);
        res.x = fmaf(wy, bot.x - top.x, top.x);
        res.y = fmaf(wy, bot.y - top.y, top.y);
        res.z = fmaf(wy, bot.z - top.z, top.z);
        res.w = fmaf(wy, bot.w - top.w, top.w);

        out4[(plane + y * Wd + x) * 4 + q] = res;
    }
}

extern "C" void kernel_launch(void* const* d_in, const int* in_sizes, int n_in,
                              void* d_out, int out_size)
{
    const float* h_prev = (const float*)d_in[0];
    const float* flow   = (const float*)d_in[1];
    const float* dt     = (const float*)d_in[2];
    float* out          = (float*)d_out;

    k_zero<<<1, NTILE>>>();
    k_bin<<<NPIX / 256, 256>>>(flow, dt);

    dim3 grid(NTILE, Cd / 2, NCHUNK);   // 256 tiles x 32 ch-groups x 16 chunks
    k_gather<<<grid, 256>>>((const float4*)h_prev, (float4*)out);
    k_overflow<<<128, 256>>>((const float4*)h_prev, (float4*)out);
}